// round 6
// baseline (speedup 1.0000x reference)
#include <cuda_runtime.h>
#include <math.h>
#include <stdint.h>

// Problem constants
#define Bc    2
#define Sc    2048
#define Ec    2048
#define Hc    16
#define HDc   128
#define Mrows 4096     // B*S
#define QKV_N 6144     // 3*E
#define GK    2048     // K dim of both GEMMs

// Interleaved {hi,lo} tf32 planes (device globals: allocation-free)
__device__ uint2 g_qpl[(size_t)Mrows * QKV_N];   // qkv output planes (200 MB)
__device__ uint2 g_apl[(size_t)Mrows * GK];      // A planes: query, then attn out (64 MB)
__device__ uint2 g_bpl[(size_t)QKV_N * GK];      // B planes: Wqkv, then Wproj (96 MB)

// ---------------------------------------------------------------------------
// Helpers
// ---------------------------------------------------------------------------
__device__ __forceinline__ uint32_t f2tf32(float x) {
    uint32_t r;
    asm("cvt.rna.tf32.f32 %0, %1;" : "=r"(r) : "f"(x));
    return r;
}
__device__ __forceinline__ uint2 split_u(float x) {
    uint32_t hi = f2tf32(x);
    uint32_t lo = f2tf32(x - __uint_as_float(hi));
    return make_uint2(hi, lo);
}
__device__ __forceinline__ uint32_t smem_u32(const void* p) {
    uint32_t a;
    asm("{ .reg .u64 t; cvta.to.shared.u64 t, %1; cvt.u32.u64 %0, t; }"
        : "=r"(a) : "l"(p));
    return a;
}
__device__ __forceinline__ void cpa16(uint32_t saddr, const void* g) {
    asm volatile("cp.async.cg.shared.global [%0], [%1], 16;" :: "r"(saddr), "l"(g));
}
__device__ __forceinline__ void cpa_commit() {
    asm volatile("cp.async.commit_group;" ::: "memory");
}
__device__ __forceinline__ void cpa_wait0() {
    asm volatile("cp.async.wait_group 0;" ::: "memory");
}
__device__ __forceinline__ void cpa_wait1() {
    asm volatile("cp.async.wait_group 1;" ::: "memory");
}
__device__ __forceinline__ void mma8(float* c,
                                     uint32_t a0, uint32_t a1, uint32_t a2, uint32_t a3,
                                     uint32_t b0, uint32_t b1) {
    asm volatile(
        "mma.sync.aligned.m16n8k8.row.col.f32.tf32.tf32.f32 "
        "{%0,%1,%2,%3}, {%4,%5,%6,%7}, {%8,%9}, {%0,%1,%2,%3};"
        : "+f"(c[0]), "+f"(c[1]), "+f"(c[2]), "+f"(c[3])
        : "r"(a0), "r"(a1), "r"(a2), "r"(a3), "r"(b0), "r"(b1));
}

// ---------------------------------------------------------------------------
// Split fp32 -> interleaved {hi,lo} uint2 plane
// ---------------------------------------------------------------------------
__global__ __launch_bounds__(256)
void split_pl(const float* __restrict__ X, uint2* __restrict__ P, size_t n)
{
    size_t i = ((size_t)blockIdx.x * 256 + threadIdx.x) << 2;
    if (i < n) {
        float4 v = *(const float4*)&X[i];
        uint2 e0 = split_u(v.x), e1 = split_u(v.y);
        uint2 e2 = split_u(v.z), e3 = split_u(v.w);
        *(uint4*)&P[i]     = make_uint4(e0.x, e0.y, e1.x, e1.y);
        *(uint4*)&P[i + 2] = make_uint4(e2.x, e2.y, e3.x, e3.y);
    }
}

// ---------------------------------------------------------------------------
// 3xTF32 GEMM from interleaved planes, cp.async staging, 2 CTAs/SM.
// C[M,N] = A[M,K] @ B[N,K]^T + bias[N].
// mode 0: write split uint2 planes to Cpl; mode 1: write fp32 to Cf.
// ---------------------------------------------------------------------------
#define SPAD 36

__global__ __launch_bounds__(256, 2)
void gemm_planes2(const uint2* __restrict__ Apl,
                  const uint2* __restrict__ Bpl,
                  const float* __restrict__ bias,
                  uint2* __restrict__ Cpl,
                  float* __restrict__ Cf,
                  int Ndim, int mode)
{
    extern __shared__ uint2 smg[];
    uint2* As = smg;
    uint2* Bs = smg + 128 * SPAD;

    const int tid  = threadIdx.x;
    const int lane = tid & 31;
    const int wid  = tid >> 5;
    const int m_off = (wid & 1) << 6;
    const int n_off = (wid >> 1) << 5;
    const int bm = blockIdx.y << 7;
    const int bn = blockIdx.x << 7;

    float c[4][4][4];
#pragma unroll
    for (int mt = 0; mt < 4; mt++)
#pragma unroll
        for (int nt = 0; nt < 4; nt++)
#pragma unroll
            for (int e = 0; e < 4; e++) c[mt][nt][e] = 0.f;

    // copy mapping: 2 threads per row, 8 chunks (16B = 2 uint2) each
    const int crow = tid >> 1;
    const int jb   = (tid & 1) << 3;
    const uint2* Asrc = Apl + (size_t)(bm + crow) * GK;
    const uint2* Bsrc = Bpl + (size_t)(bn + crow) * GK;
    const uint32_t adst = smem_u32(As) + (uint32_t)(crow * SPAD) * 8u;
    const uint32_t bdst = adst + 128u * SPAD * 8u;

#pragma unroll 1
    for (int step = 0; step < GK / 32; step++) {
        const int k0 = step * 32;
#pragma unroll
        for (int j = 0; j < 8; j++) {
            int c2 = (jb + j) << 1;
            cpa16(adst + (uint32_t)c2 * 8u, Asrc + k0 + c2);
            cpa16(bdst + (uint32_t)c2 * 8u, Bsrc + k0 + c2);
        }
        cpa_commit();
        cpa_wait0();
        __syncthreads();

#pragma unroll
        for (int kk = 0; kk < 4; kk++) {
            const int kc = (kk << 3) + (lane & 3);
            uint2 b[4][2];
#pragma unroll
            for (int nt = 0; nt < 4; nt++) {
                int n0 = n_off + nt * 8 + (lane >> 2);
                b[nt][0] = Bs[n0 * SPAD + kc];
                b[nt][1] = Bs[n0 * SPAD + kc + 4];
            }
#pragma unroll
            for (int mh = 0; mh < 2; mh++) {
                uint2 a[2][4];
#pragma unroll
                for (int i = 0; i < 2; i++) {
                    int r0 = m_off + (mh * 2 + i) * 16 + (lane >> 2);
                    a[i][0] = As[r0 * SPAD + kc];
                    a[i][1] = As[(r0 + 8) * SPAD + kc];
                    a[i][2] = As[r0 * SPAD + kc + 4];
                    a[i][3] = As[(r0 + 8) * SPAD + kc + 4];
                }
#pragma unroll
                for (int i = 0; i < 2; i++)
#pragma unroll
                    for (int nt = 0; nt < 4; nt++) {
                        float* cc = c[mh * 2 + i][nt];
                        mma8(cc, a[i][0].x, a[i][1].x, a[i][2].x, a[i][3].x,
                                 b[nt][0].x, b[nt][1].x);
                        mma8(cc, a[i][0].x, a[i][1].x, a[i][2].x, a[i][3].x,
                                 b[nt][0].y, b[nt][1].y);
                        mma8(cc, a[i][0].y, a[i][1].y, a[i][2].y, a[i][3].y,
                                 b[nt][0].x, b[nt][1].x);
                    }
            }
        }
        __syncthreads();
    }

    // epilogue
#pragma unroll
    for (int mt = 0; mt < 4; mt++) {
        int r0 = bm + m_off + mt * 16 + (lane >> 2);
#pragma unroll
        for (int nt = 0; nt < 4; nt++) {
            int col = bn + n_off + nt * 8 + ((lane & 3) << 1);
            float b0 = bias[col], b1 = bias[col + 1];
            float v00 = c[mt][nt][0] + b0, v01 = c[mt][nt][1] + b1;
            float v10 = c[mt][nt][2] + b0, v11 = c[mt][nt][3] + b1;
            if (mode == 0) {
                uint2 e0 = split_u(v00), e1 = split_u(v01);
                uint2 e2 = split_u(v10), e3 = split_u(v11);
                *(uint4*)&Cpl[(size_t)r0 * Ndim + col] =
                    make_uint4(e0.x, e0.y, e1.x, e1.y);
                *(uint4*)&Cpl[(size_t)(r0 + 8) * Ndim + col] =
                    make_uint4(e2.x, e2.y, e3.x, e3.y);
            } else {
                *(float2*)&Cf[(size_t)r0 * Ndim + col]       = make_float2(v00, v01);
                *(float2*)&Cf[(size_t)(r0 + 8) * Ndim + col] = make_float2(v10, v11);
            }
        }
    }
}

// ---------------------------------------------------------------------------
// Flash attention on mma.sync 3xTF32, operands from interleaved planes.
// CTA: 64 q-rows, K tiles of 32 (double-buffered cp.async), 256 threads.
// Smem layout (uint2 units):
//   Qpl 0 (64x132), Kpl 8448 (2 x 32x132), Vpl 16896 (2 x 32x140),
//   Ppl 25856 (64x36), state floats at 28160 (m/l/alpha, 64 each).
// Total 226048 bytes.
// ---------------------------------------------------------------------------
#define QST 132
#define VST 140
#define PST 36
#define KBUF 4224
#define VBUF 4480
#define FL_SMEM_BYTES 226048

__global__ __launch_bounds__(256)
void flash_mma2()
{
    extern __shared__ uint2 sm[];
    uint2* Qpl = sm;
    uint2* Kpl = sm + 8448;
    uint2* Vpl = sm + 16896;
    uint2* Ppl = sm + 25856;
    float* Pf  = (float*)Ppl;            // score view: Pf[2*idx]
    float* stf = (float*)(sm + 28160);
    float* m_s  = stf;
    float* l_s  = stf + 64;
    float* al_s = stf + 128;

    const int tid = threadIdx.x, lane = tid & 31, w = tid >> 5;
    const int b = blockIdx.z, h = blockIdx.y;
    const int q0 = blockIdx.x << 6;

    const uint32_t k_u = smem_u32(Kpl);
    const uint32_t v_u = smem_u32(Vpl);

    // ---- Load Q planes (64 x 128 uint2), plain vector loads ----
    {
        int row = tid >> 2;
        int cb  = (tid & 3) << 5;
        const uint2* qp = &g_qpl[((size_t)(b*Sc + q0 + row)) * QKV_N + h*384 + cb];
#pragma unroll
        for (int j = 0; j < 16; j++)
            *(uint4*)&Qpl[row*QST + cb + 2*j] = *(const uint4*)(qp + 2*j);
    }
    if (tid < 64) { m_s[tid] = -INFINITY; l_s[tid] = 0.f; }

    // copy mapping for K/V tiles: row = tid>>3, 8 chunks of 16B per plane
    const int krow = tid >> 3;
    const int kjb  = (tid & 7) << 3;

    // issue tile 0 copy
    {
        const uint2* src = &g_qpl[((size_t)(b*Sc + krow)) * QKV_N + h*384 + 128];
#pragma unroll
        for (int j = 0; j < 8; j++) {
            int c2 = (kjb + j) << 1;
            cpa16(k_u + (uint32_t)(krow*QST + c2) * 8u, src + c2);
            cpa16(v_u + (uint32_t)(krow*VST + c2) * 8u, src + 128 + c2);
        }
        cpa_commit();
    }

    float o[2][4][4];
#pragma unroll
    for (int mt = 0; mt < 2; mt++)
#pragma unroll
        for (int nt = 0; nt < 4; nt++)
#pragma unroll
            for (int e = 0; e < 4; e++) o[mt][nt][e] = 0.f;

    const int qk_m0 = (w & 3) << 4;
    const int qk_n0 = (w >> 2) << 4;
    const int pv_m0 = (w & 1) << 5;
    const int pv_n0 = (w >> 1) << 5;
    const float scale = 11.3137084989847604f;  // HD**0.5 (reference MULTIPLIES)
    const int NT = Sc / 32;

#pragma unroll 1
    for (int kt = 0; kt < NT; kt++) {
        const int s = kt & 1;
        // issue next tile copy into other buffer
        if (kt + 1 < NT) {
            const int s2 = (kt + 1) & 1;
            const uint2* src = &g_qpl[((size_t)(b*Sc + (kt+1)*32 + krow)) * QKV_N
                                      + h*384 + 128];
#pragma unroll
            for (int j = 0; j < 8; j++) {
                int c2 = (kjb + j) << 1;
                cpa16(k_u + (uint32_t)(s2*KBUF + krow*QST + c2) * 8u, src + c2);
                cpa16(v_u + (uint32_t)(s2*VBUF + krow*VST + c2) * 8u, src + 128 + c2);
            }
            cpa_commit();
            cpa_wait1();
        } else {
            cpa_wait0();
        }
        __syncthreads();

        const uint2* Kb = Kpl + s * KBUF;
        const uint2* Vb = Vpl + s * VBUF;

        // ---- S = Q @ K^T (3xTF32) ----
        float sf[2][4];
#pragma unroll
        for (int j = 0; j < 2; j++)
#pragma unroll
            for (int e = 0; e < 4; e++) sf[j][e] = 0.f;

#pragma unroll
        for (int kk = 0; kk < 16; kk++) {
            const int kc = (kk << 3) + (lane & 3);
            const int ar = qk_m0 + (lane >> 2);
            uint2 a0 = Qpl[ar*QST + kc],     a1 = Qpl[(ar+8)*QST + kc];
            uint2 a2 = Qpl[ar*QST + kc + 4], a3 = Qpl[(ar+8)*QST + kc + 4];
#pragma unroll
            for (int j = 0; j < 2; j++) {
                int n0 = qk_n0 + (j << 3) + (lane >> 2);
                uint2 b0 = Kb[n0*QST + kc], b1 = Kb[n0*QST + kc + 4];
                mma8(sf[j], a0.x, a1.x, a2.x, a3.x, b0.x, b1.x);
                mma8(sf[j], a0.x, a1.x, a2.x, a3.x, b0.y, b1.y);
                mma8(sf[j], a0.y, a1.y, a2.y, a3.y, b0.x, b1.x);
            }
        }
        {
            int r0 = qk_m0 + (lane >> 2);
            int cc = (lane & 3) << 1;
#pragma unroll
            for (int j = 0; j < 2; j++) {
                int col = qk_n0 + (j << 3) + cc;
                Pf[(r0*PST + col) * 2]       = sf[j][0] * scale;
                Pf[(r0*PST + col + 1) * 2]   = sf[j][1] * scale;
                Pf[((r0+8)*PST + col) * 2]   = sf[j][2] * scale;
                Pf[((r0+8)*PST + col + 1) * 2] = sf[j][3] * scale;
            }
        }
        __syncthreads();

        // ---- online softmax: warp w rows 8w..8w+7 ----
#pragma unroll 1
        for (int rr = 0; rr < 8; rr++) {
            int r = (w << 3) + rr;
            float sv = Pf[(r*PST + lane) * 2];
            float mx = sv;
#pragma unroll
            for (int off = 16; off > 0; off >>= 1)
                mx = fmaxf(mx, __shfl_xor_sync(0xffffffffu, mx, off));
            float mo = m_s[r];
            float mn = fmaxf(mo, mx);
            float p = __expf(sv - mn);
            float psum = p;
#pragma unroll
            for (int off = 16; off > 0; off >>= 1)
                psum += __shfl_xor_sync(0xffffffffu, psum, off);
            Ppl[r*PST + lane] = split_u(p);
            if (lane == 0) {
                float al = (mo == -INFINITY) ? 0.f : __expf(mo - mn);
                al_s[r] = al;
                l_s[r]  = l_s[r]*al + psum;
                m_s[r]  = mn;
            }
        }
        __syncthreads();

        // ---- O = O*alpha + P @ V (3xTF32) ----
#pragma unroll
        for (int mt = 0; mt < 2; mt++) {
            float a0 = al_s[pv_m0 + (mt << 4) + (lane >> 2)];
            float a1 = al_s[pv_m0 + (mt << 4) + 8 + (lane >> 2)];
#pragma unroll
            for (int nt = 0; nt < 4; nt++) {
                o[mt][nt][0] *= a0; o[mt][nt][1] *= a0;
                o[mt][nt][2] *= a1; o[mt][nt][3] *= a1;
            }
        }
#pragma unroll
        for (int kk = 0; kk < 4; kk++) {
            const int kc = (kk << 3) + (lane & 3);
            uint2 ap[2][4];
#pragma unroll
            for (int mt = 0; mt < 2; mt++) {
                int r0 = pv_m0 + (mt << 4) + (lane >> 2);
                ap[mt][0] = Ppl[r0*PST + kc];     ap[mt][1] = Ppl[(r0+8)*PST + kc];
                ap[mt][2] = Ppl[r0*PST + kc + 4]; ap[mt][3] = Ppl[(r0+8)*PST + kc + 4];
            }
#pragma unroll
            for (int nt = 0; nt < 4; nt++) {
                int n0 = pv_n0 + (nt << 3) + (lane >> 2);
                uint2 v0 = Vb[kc*VST + n0];
                uint2 v1 = Vb[(kc + 4)*VST + n0];
#pragma unroll
                for (int mt = 0; mt < 2; mt++) {
                    mma8(o[mt][nt], ap[mt][0].x, ap[mt][1].x, ap[mt][2].x, ap[mt][3].x,
                                    v0.x, v1.x);
                    mma8(o[mt][nt], ap[mt][0].x, ap[mt][1].x, ap[mt][2].x, ap[mt][3].x,
                                    v0.y, v1.y);
                    mma8(o[mt][nt], ap[mt][0].y, ap[mt][1].y, ap[mt][2].y, ap[mt][3].y,
                                    v0.x, v1.x);
                }
            }
        }
        __syncthreads();   // protect buffers + Ppl for next iteration
    }

    // ---- epilogue: normalize, split, store planes to g_apl ----
#pragma unroll
    for (int mt = 0; mt < 2; mt++) {
        int r0 = pv_m0 + (mt << 4) + (lane >> 2);
        float i0 = 1.f / l_s[r0];
        float i1 = 1.f / l_s[r0 + 8];
        size_t g0 = ((size_t)(b*Sc + q0 + r0)) * GK + h*HDc;
        size_t g1 = ((size_t)(b*Sc + q0 + r0 + 8)) * GK + h*HDc;
#pragma unroll
        for (int nt = 0; nt < 4; nt++) {
            int col = pv_n0 + (nt << 3) + ((lane & 3) << 1);
            uint2 e0 = split_u(o[mt][nt][0] * i0);
            uint2 e1 = split_u(o[mt][nt][1] * i0);
            uint2 e2 = split_u(o[mt][nt][2] * i1);
            uint2 e3 = split_u(o[mt][nt][3] * i1);
            *(uint4*)&g_apl[g0 + col] = make_uint4(e0.x, e0.y, e1.x, e1.y);
            *(uint4*)&g_apl[g1 + col] = make_uint4(e2.x, e2.y, e3.x, e3.y);
        }
    }
}

// ---------------------------------------------------------------------------
extern "C" void kernel_launch(void* const* d_in, const int* in_sizes, int n_in,
                              void* d_out, int out_size)
{
    const float* query = (const float*)d_in[0];
    const float* Wqkv  = (const float*)d_in[3];
    const float* bqkv  = (const float*)d_in[4];
    const float* Wproj = (const float*)d_in[5];
    const float* bproj = (const float*)d_in[6];
    float* out = (float*)d_out;

    uint2 *qpl, *apl, *bpl;
    cudaGetSymbolAddress((void**)&qpl, g_qpl);
    cudaGetSymbolAddress((void**)&apl, g_apl);
    cudaGetSymbolAddress((void**)&bpl, g_bpl);

    const int gemm_smem = 2 * 128 * SPAD * (int)sizeof(uint2);  // 73728
    cudaFuncSetAttribute(gemm_planes2,
                         cudaFuncAttributeMaxDynamicSharedMemorySize, gemm_smem);
    cudaFuncSetAttribute(flash_mma2,
                         cudaFuncAttributeMaxDynamicSharedMemorySize, FL_SMEM_BYTES);

    const size_t nA  = (size_t)Mrows * GK;    // 8M
    const size_t nB1 = (size_t)QKV_N * GK;    // 12M
    const size_t nB2 = (size_t)Ec * GK;       // 4M

    // 0) split inputs into interleaved planes
    split_pl<<<(int)(nA  / 1024), 256>>>(query, apl, nA);
    split_pl<<<(int)(nB1 / 1024), 256>>>(Wqkv,  bpl, nB1);

    // 1) qkv GEMM -> split planes directly (mode 0)
    gemm_planes2<<<dim3(QKV_N/128, Mrows/128), 256, gemm_smem>>>(
        apl, bpl, bqkv, qpl, nullptr, QKV_N, 0);

    // 2) flash attention -> split planes directly into g_apl
    flash_mma2<<<dim3(Sc/64, Hc, Bc), 256, FL_SMEM_BYTES>>>();

    // 2b) split Wproj
    split_pl<<<(int)(nB2 / 1024), 256>>>(Wproj, bpl, nB2);

    // 3) proj GEMM -> fp32 output (mode 1)
    gemm_planes2<<<dim3(Ec/128, Mrows/128), 256, gemm_smem>>>(
        apl, bpl, bproj, nullptr, out, Ec, 1);
}

// round 7
// speedup vs baseline: 1.3205x; 1.3205x over previous
#include <cuda_runtime.h>
#include <math.h>
#include <stdint.h>

// Problem constants
#define Bc    2
#define Sc    2048
#define Ec    2048
#define Hc    16
#define HDc   128
#define Mrows 4096     // B*S
#define QKV_N 6144     // 3*E
#define GK    2048     // K dim of both GEMMs

// Scratch (device globals: allocation-free per harness rules)
__device__ float g_qkv[(size_t)Mrows * QKV_N];   // ~100 MB
__device__ float g_attn[(size_t)Mrows * Ec];     // ~33 MB

// ---------------------------------------------------------------------------
// Helpers
// ---------------------------------------------------------------------------
__device__ __forceinline__ uint32_t f2tf32(float x) {
    uint32_t r;
    asm("cvt.rna.tf32.f32 %0, %1;" : "=r"(r) : "f"(x));
    return r;
}
__device__ __forceinline__ uint2 split_tf32(float x) {
    uint32_t hi = f2tf32(x);
    uint32_t lo = f2tf32(x - __uint_as_float(hi));
    return make_uint2(hi, lo);
}
__device__ __forceinline__ void mma8(float* c,
                                     uint32_t a0, uint32_t a1, uint32_t a2, uint32_t a3,
                                     uint32_t b0, uint32_t b1) {
    asm volatile(
        "mma.sync.aligned.m16n8k8.row.col.f32.tf32.tf32.f32 "
        "{%0,%1,%2,%3}, {%4,%5,%6,%7}, {%8,%9}, {%0,%1,%2,%3};"
        : "+f"(c[0]), "+f"(c[1]), "+f"(c[2]), "+f"(c[3])
        : "r"(a0), "r"(a1), "r"(a2), "r"(a3), "r"(b0), "r"(b1));
}

// ---------------------------------------------------------------------------
// 3xTF32 tensor-core GEMM, 512 threads (16 warps), warp tile 32x32.
// C[M,N] = A[M,K] @ B[N,K]^T + bias[N], 128x128 CTA tile, BK=32.
// Same smem layout + arithmetic as the proven R2 kernel; only the thread
// decomposition changed (occupancy 8 -> 16 warps/SM).
// ---------------------------------------------------------------------------
#define SPAD 36          // row stride in uint2 (conflict-free: 4q+t distinct)

__global__ __launch_bounds__(512)
void gemm_tf32x3_w16(const float* __restrict__ A,
                     const float* __restrict__ Bw,
                     const float* __restrict__ bias,
                     float* __restrict__ C,
                     int Ndim)
{
    extern __shared__ uint2 sm2[];
    uint2* As = sm2;                 // [128][SPAD]
    uint2* Bs = sm2 + 128 * SPAD;

    const int tid   = threadIdx.x;
    const int lane  = tid & 31;
    const int wid   = tid >> 5;          // 0..15
    const int m_off = (wid & 3) << 5;    // 0,32,64,96
    const int n_off = (wid >> 2) << 5;   // 0,32,64,96
    const int bm    = blockIdx.y << 7;
    const int bn    = blockIdx.x << 7;

    // loader mapping: one row per 4 threads, 8 consecutive k's each
    const int lrow = tid >> 2;           // 0..127
    const int lcol = (tid & 3) << 3;     // 0,8,16,24

    float c[2][4][4];
#pragma unroll
    for (int mt = 0; mt < 2; mt++)
#pragma unroll
        for (int nt = 0; nt < 4; nt++)
#pragma unroll
            for (int e = 0; e < 4; e++) c[mt][nt][e] = 0.f;

    float4 pa[2], pb[2];
#pragma unroll
    for (int j = 0; j < 2; j++) {
        pa[j] = *(const float4*)&A [(size_t)(bm + lrow) * GK + lcol + 4*j];
        pb[j] = *(const float4*)&Bw[(size_t)(bn + lrow) * GK + lcol + 4*j];
    }

    const int nsteps = GK / 32;
#pragma unroll 1
    for (int step = 0; step < nsteps; step++) {
        __syncthreads();
#pragma unroll
        for (int j = 0; j < 2; j++) {
            float av[4] = {pa[j].x, pa[j].y, pa[j].z, pa[j].w};
            float bv[4] = {pb[j].x, pb[j].y, pb[j].z, pb[j].w};
            uint2 ah[4], bh[4];
#pragma unroll
            for (int e = 0; e < 4; e++) { ah[e] = split_tf32(av[e]); bh[e] = split_tf32(bv[e]); }
            int base = lrow * SPAD + lcol + 4*j;
            *(uint4*)&As[base    ] = make_uint4(ah[0].x, ah[0].y, ah[1].x, ah[1].y);
            *(uint4*)&As[base + 2] = make_uint4(ah[2].x, ah[2].y, ah[3].x, ah[3].y);
            *(uint4*)&Bs[base    ] = make_uint4(bh[0].x, bh[0].y, bh[1].x, bh[1].y);
            *(uint4*)&Bs[base + 2] = make_uint4(bh[2].x, bh[2].y, bh[3].x, bh[3].y);
        }
        __syncthreads();

        if (step + 1 < nsteps) {
            int k0 = (step + 1) * 32;
#pragma unroll
            for (int j = 0; j < 2; j++) {
                pa[j] = *(const float4*)&A [(size_t)(bm + lrow) * GK + k0 + lcol + 4*j];
                pb[j] = *(const float4*)&Bw[(size_t)(bn + lrow) * GK + k0 + lcol + 4*j];
            }
        }

#pragma unroll
        for (int kk = 0; kk < 4; kk++) {
            const int kc = (kk << 3) + (lane & 3);
            uint2 a[2][4];
#pragma unroll
            for (int mt = 0; mt < 2; mt++) {
                int r0 = m_off + mt * 16 + (lane >> 2);
                a[mt][0] = As[r0 * SPAD + kc];
                a[mt][1] = As[(r0 + 8) * SPAD + kc];
                a[mt][2] = As[r0 * SPAD + kc + 4];
                a[mt][3] = As[(r0 + 8) * SPAD + kc + 4];
            }
            uint2 b[4][2];
#pragma unroll
            for (int nt = 0; nt < 4; nt++) {
                int n0 = n_off + nt * 8 + (lane >> 2);
                b[nt][0] = Bs[n0 * SPAD + kc];
                b[nt][1] = Bs[n0 * SPAD + kc + 4];
            }
#pragma unroll
            for (int mt = 0; mt < 2; mt++)
#pragma unroll
                for (int nt = 0; nt < 4; nt++) {
                    mma8(c[mt][nt], a[mt][0].x, a[mt][1].x, a[mt][2].x, a[mt][3].x,
                                    b[nt][0].x, b[nt][1].x);
                    mma8(c[mt][nt], a[mt][0].x, a[mt][1].x, a[mt][2].x, a[mt][3].x,
                                    b[nt][0].y, b[nt][1].y);
                    mma8(c[mt][nt], a[mt][0].y, a[mt][1].y, a[mt][2].y, a[mt][3].y,
                                    b[nt][0].x, b[nt][1].x);
                }
        }
    }

#pragma unroll
    for (int mt = 0; mt < 2; mt++) {
        int r0 = bm + m_off + mt * 16 + (lane >> 2);
#pragma unroll
        for (int nt = 0; nt < 4; nt++) {
            int col = bn + n_off + nt * 8 + ((lane & 3) << 1);
            float b0 = bias[col], b1 = bias[col + 1];
            *(float2*)&C[(size_t)r0 * Ndim + col] =
                make_float2(c[mt][nt][0] + b0, c[mt][nt][1] + b1);
            *(float2*)&C[(size_t)(r0 + 8) * Ndim + col] =
                make_float2(c[mt][nt][2] + b0, c[mt][nt][3] + b1);
        }
    }
}

// ---------------------------------------------------------------------------
// Flash attention, fp32 SIMT (proven R1 kernel, 2.34 ms)
// ---------------------------------------------------------------------------
#define SQt 128
#define SKt 64
#define DP  132

__global__ __launch_bounds__(256)
void flash_fp32()
{
    extern __shared__ float smf[];
    float* Qs   = smf;
    float* Ks   = Qs  + SQt*DP;
    float* Vs   = Ks  + SKt*DP;
    float* Ps   = Vs  + SKt*DP;
    float* m_s  = Ps  + SQt*SKt;
    float* l_s  = m_s + SQt;
    float* al_s = l_s + SQt;

    const int tid  = threadIdx.x;
    const int lane = tid & 31, wid = tid >> 5;
    const int ty   = tid >> 4, tx  = tid & 15;
    const int b = blockIdx.z, h = blockIdx.y;
    const int q0 = blockIdx.x << 7;

    const size_t qbase = ((size_t)(b*Sc + q0)) * QKV_N + h*384;

#pragma unroll
    for (int i = 0; i < 16; i++) {
        int idx = tid + (i << 8);
        int r   = idx >> 5;
        int c4  = (idx & 31) << 2;
        *(float4*)&Qs[r*DP + c4] =
            *(const float4*)&g_qkv[qbase + (size_t)r*QKV_N + c4];
    }
    if (tid < SQt) { m_s[tid] = -INFINITY; l_s[tid] = 0.f; }

    float o[8][8];
#pragma unroll
    for (int i = 0; i < 8; i++)
#pragma unroll
        for (int c = 0; c < 8; c++) o[i][c] = 0.f;

    const float scale = 11.3137084989847604f;  // HD**0.5 (reference MULTIPLIES)

    for (int kt = 0; kt < Sc; kt += SKt) {
        __syncthreads();
        const size_t kbase = ((size_t)(b*Sc + kt)) * QKV_N + h*384;
#pragma unroll
        for (int i = 0; i < 8; i++) {
            int idx = tid + (i << 8);
            int r   = idx >> 5;
            int c4  = (idx & 31) << 2;
            *(float4*)&Ks[r*DP + c4] =
                *(const float4*)&g_qkv[kbase + (size_t)r*QKV_N + 128 + c4];
            *(float4*)&Vs[r*DP + c4] =
                *(const float4*)&g_qkv[kbase + (size_t)r*QKV_N + 256 + c4];
        }
        __syncthreads();

        float s[8][4];
#pragma unroll
        for (int i = 0; i < 8; i++)
#pragma unroll
            for (int c = 0; c < 4; c++) s[i][c] = 0.f;

#pragma unroll 8
        for (int d = 0; d < HDc; d += 4) {
            float4 kf[4];
#pragma unroll
            for (int c = 0; c < 4; c++)
                kf[c] = *(const float4*)&Ks[(tx + 16*c)*DP + d];
#pragma unroll
            for (int i = 0; i < 8; i++) {
                float4 qf = *(const float4*)&Qs[(8*ty + i)*DP + d];
#pragma unroll
                for (int c = 0; c < 4; c++)
                    s[i][c] += qf.x*kf[c].x + qf.y*kf[c].y
                             + qf.z*kf[c].z + qf.w*kf[c].w;
            }
        }
#pragma unroll
        for (int i = 0; i < 8; i++)
#pragma unroll
            for (int c = 0; c < 4; c++)
                Ps[(8*ty + i)*SKt + tx + 16*c] = s[i][c] * scale;
        __syncthreads();

#pragma unroll 1
        for (int rr = 0; rr < 16; rr++) {
            int r = wid*16 + rr;
            float s0 = Ps[r*SKt + lane];
            float s1 = Ps[r*SKt + 32 + lane];
            float mx = fmaxf(s0, s1);
#pragma unroll
            for (int off = 16; off > 0; off >>= 1)
                mx = fmaxf(mx, __shfl_xor_sync(0xffffffffu, mx, off));
            float mo = m_s[r];
            float mn = fmaxf(mo, mx);
            float p0 = __expf(s0 - mn);
            float p1 = __expf(s1 - mn);
            float ps = p0 + p1;
#pragma unroll
            for (int off = 16; off > 0; off >>= 1)
                ps += __shfl_xor_sync(0xffffffffu, ps, off);
            Ps[r*SKt + lane]      = p0;
            Ps[r*SKt + 32 + lane] = p1;
            if (lane == 0) {
                float al = (mo == -INFINITY) ? 0.f : __expf(mo - mn);
                al_s[r] = al;
                l_s[r]  = l_s[r]*al + ps;
                m_s[r]  = mn;
            }
        }
        __syncthreads();

        float al[8];
#pragma unroll
        for (int i = 0; i < 8; i++) al[i] = al_s[8*ty + i];
#pragma unroll
        for (int i = 0; i < 8; i++)
#pragma unroll
            for (int c = 0; c < 8; c++) o[i][c] *= al[i];

#pragma unroll 4
        for (int j = 0; j < SKt; j++) {
            float p[8], v[8];
#pragma unroll
            for (int i = 0; i < 8; i++) p[i] = Ps[(8*ty + i)*SKt + j];
#pragma unroll
            for (int c = 0; c < 8; c++) v[c] = Vs[j*DP + tx + 16*c];
#pragma unroll
            for (int i = 0; i < 8; i++)
#pragma unroll
                for (int c = 0; c < 8; c++)
                    o[i][c] += p[i]*v[c];
        }
    }

#pragma unroll
    for (int i = 0; i < 8; i++) {
        int r = 8*ty + i;
        float inv = 1.0f / l_s[r];
        size_t obase = ((size_t)(b*Sc + q0 + r)) * Ec + h*HDc;
#pragma unroll
        for (int c = 0; c < 8; c++)
            g_attn[obase + tx + 16*c] = o[i][c] * inv;
    }
}

// ---------------------------------------------------------------------------
extern "C" void kernel_launch(void* const* d_in, const int* in_sizes, int n_in,
                              void* d_out, int out_size)
{
    const float* query = (const float*)d_in[0];
    const float* Wqkv  = (const float*)d_in[3];
    const float* bqkv  = (const float*)d_in[4];
    const float* Wproj = (const float*)d_in[5];
    const float* bproj = (const float*)d_in[6];
    float* out = (float*)d_out;

    float *qkvp = nullptr, *attnp = nullptr;
    cudaGetSymbolAddress((void**)&qkvp,  g_qkv);
    cudaGetSymbolAddress((void**)&attnp, g_attn);

    const int gemm_smem = 2 * 128 * SPAD * (int)sizeof(uint2);  // 73728
    cudaFuncSetAttribute(gemm_tf32x3_w16,
                         cudaFuncAttributeMaxDynamicSharedMemorySize, gemm_smem);

    // 1) qkv = query @ Wqkv^T + bqkv
    gemm_tf32x3_w16<<<dim3(QKV_N/128, Mrows/128), 512, gemm_smem>>>(
        query, Wqkv, bqkv, qkvp, QKV_N);

    // 2) flash attention -> g_attn
    const int fl_smem = (SQt*DP + 2*SKt*DP + SQt*SKt + 3*SQt) * (int)sizeof(float);
    cudaFuncSetAttribute(flash_fp32,
                         cudaFuncAttributeMaxDynamicSharedMemorySize, fl_smem);
    flash_fp32<<<dim3(Sc/128, Hc, Bc), 256, fl_smem>>>();

    // 3) out = attn @ Wproj^T + bproj
    gemm_tf32x3_w16<<<dim3(Ec/128, Mrows/128), 512, gemm_smem>>>(
        attnp, Wproj, bproj, out, Ec);
}